// round 5
// baseline (speedup 1.0000x reference)
#include <cuda_runtime.h>
#include <cstdint>

#define B_ 256
#define S_ 512
#define H_ 512
#define V_ 50257
#define VP_ 50304
#define EPS_ 1e-40f
#define SKR 36
#define BK 32

__device__ float g_logits[(size_t)B_ * VP_];
__device__ float g_ctx_part[8 * B_ * 1024];
__device__ float g_row_M[B_];
__device__ float g_row_S[B_];
__device__ float g_pgen[B_];

static __device__ __forceinline__ uint32_t smem_u32(const void* p) {
    uint32_t r;
    asm("{ .reg .u64 t; cvta.to.shared.u64 t, %1; cvt.u32.u64 %0, t; }" : "=r"(r) : "l"(p));
    return r;
}
static __device__ __forceinline__ void cp16(uint32_t dst, const void* src, int nbytes) {
    asm volatile("cp.async.cg.shared.global [%0], [%1], 16, %2;"
                 :: "r"(dst), "l"(src), "r"(nbytes) : "memory");
}
#define CP_COMMIT() asm volatile("cp.async.commit_group;" ::: "memory")
#define CP_WAIT(n)  asm volatile("cp.async.wait_group %0;" ::"n"(n) : "memory")

static __device__ __forceinline__ uint32_t tf32c(float f) {
    uint32_t r;
    asm("cvt.rna.tf32.f32 %0, %1;" : "=r"(r) : "f"(f));
    return r;
}
static __device__ __forceinline__ void mma8(float* c, const uint32_t* a, uint32_t b0, uint32_t b1) {
    asm volatile(
        "mma.sync.aligned.m16n8k8.row.col.f32.tf32.tf32.f32 "
        "{%0,%1,%2,%3},{%4,%5,%6,%7},{%8,%9},{%0,%1,%2,%3};"
        : "+f"(c[0]), "+f"(c[1]), "+f"(c[2]), "+f"(c[3])
        : "r"(a[0]), "r"(a[1]), "r"(a[2]), "r"(a[3]), "r"(b0), "r"(b1));
}

// ---- K1: context partials  ctx[b,h] = sum_s attn[b,s]*enc[s,b,h], S split 8 ----
__global__ void __launch_bounds__(256) k_ctx(const float* __restrict__ enc,
                                             const float* __restrict__ attn) {
    const int b = blockIdx.x, split = blockIdx.y, tid = threadIdx.x;
    __shared__ float sa[64];
    const int s0 = split * 64;
    if (tid < 64) sa[tid] = attn[b * S_ + s0 + tid];
    __syncthreads();
    const float4* ep = reinterpret_cast<const float4*>(enc) + ((size_t)s0 * B_ + b) * 256 + tid;
    float4 acc = make_float4(0.f, 0.f, 0.f, 0.f);
#pragma unroll 4
    for (int s = 0; s < 64; s++) {
        float a = sa[s];
        float4 e = ep[(size_t)s * (B_ * 256)];
        acc.x = fmaf(a, e.x, acc.x); acc.y = fmaf(a, e.y, acc.y);
        acc.z = fmaf(a, e.z, acc.z); acc.w = fmaf(a, e.w, acc.w);
    }
    reinterpret_cast<float4*>(g_ctx_part)[((size_t)split * B_ + b) * 256 + tid] = acc;
}

// ---- K2: reduce ctx partials + p_gen = sigmoid([hid,emb,ctx]·w + b) ----
__global__ void __launch_bounds__(256) k_pgen(const float* __restrict__ hid,
                                              const float* __restrict__ emb,
                                              const float* __restrict__ pw,
                                              const float* __restrict__ pb) {
    const int b = blockIdx.x, tid = threadIdx.x;
    float4 c = make_float4(0.f, 0.f, 0.f, 0.f);
#pragma unroll
    for (int sp = 0; sp < 8; sp++) {
        float4 p = reinterpret_cast<const float4*>(g_ctx_part)[((size_t)sp * B_ + b) * 256 + tid];
        c.x += p.x; c.y += p.y; c.z += p.z; c.w += p.w;
    }
    float4 w = reinterpret_cast<const float4*>(pw + 1024)[tid];
    float loc = c.x * w.x + c.y * w.y + c.z * w.z + c.w * w.w;
    loc += hid[b * H_ + tid] * pw[tid] + hid[b * H_ + tid + 256] * pw[tid + 256];
    loc += emb[b * H_ + tid] * pw[512 + tid] + emb[b * H_ + tid + 256] * pw[512 + tid + 256];
#pragma unroll
    for (int o = 16; o; o >>= 1) loc += __shfl_xor_sync(~0u, loc, o);
    __shared__ float red[8];
    if ((tid & 31) == 0) red[tid >> 5] = loc;
    __syncthreads();
    if (tid == 0) {
        float z = pb[0];
#pragma unroll
        for (int i = 0; i < 8; i++) z += red[i];
        g_pgen[b] = 1.f / (1.f + __expf(-z));
    }
}

// ---- K3: logits[b,v] = x[b,:] · W[v,:] + bias[v]  (tf32 mma.sync, 128x128 tiles) ----
__global__ void __launch_bounds__(256) k_gemm(const float* __restrict__ A,
                                              const float* __restrict__ W,
                                              const float* __restrict__ bias) {
    extern __shared__ float sm[];
    const int tid = threadIdx.x;
    const int bn0 = blockIdx.x * 128, bm0 = blockIdx.y * 128;
    const int lane = tid & 31, wid = tid >> 5;
    const int wm = (wid & 1) * 64, wn = (wid >> 1) * 32;
    const int STG = 2 * 128 * SKR;

    float acc[4][4][4];
#pragma unroll
    for (int i = 0; i < 4; i++)
#pragma unroll
        for (int j = 0; j < 4; j++)
#pragma unroll
            for (int r = 0; r < 4; r++) acc[i][j][r] = 0.f;

    auto g2s = [&](int st, int k0) {
        float* As = sm + st * STG;
        float* Bs = As + 128 * SKR;
#pragma unroll
        for (int i = 0; i < 4; i++) {
            int idx = tid + i * 256;
            int r = idx >> 3, c4 = (idx & 7) << 2;
            cp16(smem_u32(&As[r * SKR + c4]), &A[(size_t)(bm0 + r) * H_ + k0 + c4], 16);
            int n = bn0 + r;
            int nn = (n < V_) ? n : (V_ - 1);
            cp16(smem_u32(&Bs[r * SKR + c4]), &W[(size_t)nn * H_ + k0 + c4], (n < V_) ? 16 : 0);
        }
    };

    g2s(0, 0); CP_COMMIT();
    const int NK = H_ / BK;
    for (int kt = 0; kt < NK; kt++) {
        if (kt + 1 < NK) { g2s((kt + 1) & 1, (kt + 1) * BK); CP_COMMIT(); CP_WAIT(1); }
        else             { CP_WAIT(0); }
        __syncthreads();
        const float* As = sm + (kt & 1) * STG;
        const float* Bs = As + 128 * SKR;
#pragma unroll
        for (int kk = 0; kk < 4; kk++) {
            const int k0 = kk * 8 + (lane & 3);
            uint32_t a[4][4];
#pragma unroll
            for (int mi = 0; mi < 4; mi++) {
                int r = wm + mi * 16 + (lane >> 2);
                a[mi][0] = tf32c(As[r * SKR + k0]);
                a[mi][1] = tf32c(As[(r + 8) * SKR + k0]);
                a[mi][2] = tf32c(As[r * SKR + k0 + 4]);
                a[mi][3] = tf32c(As[(r + 8) * SKR + k0 + 4]);
            }
#pragma unroll
            for (int ni = 0; ni < 4; ni++) {
                int c = wn + ni * 8 + (lane >> 2);
                uint32_t b0 = tf32c(Bs[c * SKR + k0]);
                uint32_t b1 = tf32c(Bs[c * SKR + k0 + 4]);
#pragma unroll
                for (int mi = 0; mi < 4; mi++) mma8(acc[mi][ni], a[mi], b0, b1);
            }
        }
        __syncthreads();
    }

#pragma unroll
    for (int mi = 0; mi < 4; mi++) {
#pragma unroll
        for (int ni = 0; ni < 4; ni++) {
            int m = bm0 + wm + mi * 16 + (lane >> 2);
            int n = bn0 + wn + ni * 8 + ((lane & 3) << 1);
            float* C = acc[mi][ni];
            if (n + 1 < V_) {
                float b0 = bias[n], b1 = bias[n + 1];
                *(float2*)&g_logits[(size_t)m * VP_ + n]       = make_float2(C[0] + b0, C[1] + b1);
                *(float2*)&g_logits[(size_t)(m + 8) * VP_ + n] = make_float2(C[2] + b0, C[3] + b1);
            } else if (n < V_) {
                float b0 = bias[n];
                g_logits[(size_t)m * VP_ + n]       = C[0] + b0;
                g_logits[(size_t)(m + 8) * VP_ + n] = C[2] + b0;
            }
        }
    }
}

// ---- K4: per-row softmax max & sum(exp) ----
__global__ void __launch_bounds__(1024) k_stats() {
    const int b = blockIdx.x, tid = threadIdx.x;
    const float* row = g_logits + (size_t)b * VP_;
    float m = -1e30f, s = 0.f;
    for (int i = tid; i < V_; i += 1024) {
        float x = row[i];
        float nm = fmaxf(m, x);
        s = s * __expf(m - nm) + __expf(x - nm);
        m = nm;
    }
#pragma unroll
    for (int o = 16; o; o >>= 1) {
        float m2 = __shfl_xor_sync(~0u, m, o), s2 = __shfl_xor_sync(~0u, s, o);
        float nm = fmaxf(m, m2);
        s = s * __expf(m - nm) + s2 * __expf(m2 - nm); m = nm;
    }
    __shared__ float sm_[32], ss_[32];
    if ((tid & 31) == 0) { sm_[tid >> 5] = m; ss_[tid >> 5] = s; }
    __syncthreads();
    if (tid < 32) {
        m = sm_[tid]; s = ss_[tid];
#pragma unroll
        for (int o = 16; o; o >>= 1) {
            float m2 = __shfl_xor_sync(~0u, m, o), s2 = __shfl_xor_sync(~0u, s, o);
            float nm = fmaxf(m, m2);
            s = s * __expf(m - nm) + s2 * __expf(m2 - nm); m = nm;
        }
        if (tid == 0) { g_row_M[b] = m; g_row_S[b] = s; }
    }
}

// ---- K5: fused combine+scatter+log: out = log(pgen*softmax + (1-pgen)*scatter(attn) + EPS) ----
__global__ void __launch_bounds__(512) k_final(const int* __restrict__ ids32,
                                               const float* __restrict__ attn,
                                               float* __restrict__ out) {
    const int b = blockIdx.x, tid = threadIdx.x;
    __shared__ int ids[S_];
    __shared__ float pat[S_];
    __shared__ uint32_t bm[VP_ / 32];
    for (int i = tid; i < VP_ / 32; i += 512) bm[i] = 0u;
    const float pg = g_pgen[b];
    __syncthreads();
    if (tid < S_) {
        int id = ids32[(size_t)b * S_ + tid];
        ids[tid] = id;
        pat[tid] = (1.f - pg) * attn[b * S_ + tid];
        atomicOr(&bm[id >> 5], 1u << (id & 31));
    }
    __syncthreads();
    const float M = g_row_M[b];
    const float invS = 1.f / g_row_S[b];
    const int v0 = blockIdx.y * 12576;
    const int v1 = (v0 + 12576 < V_) ? v0 + 12576 : V_;
    const float* lrow = g_logits + (size_t)b * VP_;
    float* orow = out + (size_t)b * V_;
#pragma unroll 4
    for (int v = v0 + tid; v < v1; v += 512) {
        float p = pg * __expf(lrow[v] - M) * invS;
        if ((bm[v >> 5] >> (v & 31)) & 1u) {
            for (int j = 0; j < S_; j++)
                if (ids[j] == v) p += pat[j];
        }
        orow[v] = __logf(p + EPS_);
    }
}

extern "C" void kernel_launch(void* const* d_in, const int* in_sizes, int n_in,
                              void* d_out, int out_size) {
    const float* x    = (const float*)d_in[0];
    const float* emb  = (const float*)d_in[1];
    const float* hid  = (const float*)d_in[2];
    const float* enc  = (const float*)d_in[3];
    const float* attn = (const float*)d_in[4];
    const int*   ids  = (const int*)d_in[5];
    const float* pw   = (const float*)d_in[6];
    const float* pb   = (const float*)d_in[7];
    const float* gw   = (const float*)d_in[8];
    const float* gb   = (const float*)d_in[9];
    float* out = (float*)d_out;

    cudaFuncSetAttribute(k_gemm, cudaFuncAttributeMaxDynamicSharedMemorySize, 73728);

    k_ctx  <<<dim3(B_, 8), 256>>>(enc, attn);
    k_pgen <<<B_, 256>>>(hid, emb, gw, gb);
    k_gemm <<<dim3((V_ + 127) / 128, 2), 256, 73728>>>(x, pw, pb);
    k_stats<<<B_, 1024>>>();
    k_final<<<dim3(B_, 4), 512>>>(ids, attn, out);
}